// round 1
// baseline (speedup 1.0000x reference)
#include <cuda_runtime.h>
#include <math.h>

#define TWO_PI 6.283185307179586f
#define EPS 1e-6f
#define NEG_HALF_LOG2E (-0.7213475204444817f)

// ---------------- device scratch (max sizes across stages) ----------------
// conv outputs: max 32*6*5*25*5 = 120000 components
#define MAXM 120000
// selected mixtures: max 32*1*64 = 2048 (input), 32*5*25 = 4000
#define MAXS 4096
#define MAXROWS 320

__device__ float g_W[MAXM], g_PX[MAXM], g_PY[MAXM];
__device__ float g_C00[MAXM], g_C01[MAXM], g_C10[MAXM], g_C11[MAXM];
__device__ float g_EA[MAXM], g_EB[MAXM], g_EC[MAXM];
__device__ float g_W2[MAXM];

__device__ float g_SW[MAXS], g_SPX[MAXS], g_SPY[MAXS];
__device__ float g_SC00[MAXS], g_SC01[MAXS], g_SC10[MAXS], g_SC11[MAXS];

__device__ float g_TOT[MAXROWS], g_SIG[MAXROWS];

__device__ __forceinline__ float fast_exp2(float x) {
    float y;
    asm("ex2.approx.ftz.f32 %0, %1;" : "=f"(y) : "f"(x));
    return y;
}

// ---------------- K1: batchnorm(per_gaussian=True) on input ----------------
// in_x: (32, 1, 64, 7). One block per b, 64 threads.
__global__ void k_bn_input(const float* __restrict__ in_x) {
    int b = blockIdx.x;
    int n = threadIdx.x; // 0..63
    const float* m = in_x + (b * 64 + n) * 7;
    float w = m[0], px = m[1], py = m[2];
    float c00 = m[3], c01 = m[4], c10 = m[5], c11 = m[6];
    float det = c00 * c11 - c01 * c10;
    float I = w * TWO_PI * sqrtf(fmaxf(det, EPS));

    __shared__ float sh[64];
    sh[n] = fabsf(I);
    __syncthreads();
    for (int s = 32; s > 0; s >>= 1) {
        if (n < s) sh[n] += sh[n + s];
        __syncthreads();
    }
    float tot = sh[0];

    int idx = b * 64 + n;
    g_SW[idx]   = w / (tot + EPS);
    g_SPX[idx]  = px;  g_SPY[idx]  = py;
    g_SC00[idx] = c00; g_SC01[idx] = c01;
    g_SC10[idx] = c10; g_SC11[idx] = c11;
}

// ---------------- conv: data (B,Li,Nd) x kernel (Lo,Li,Nk) ----------------
// output component o = (b*Lo+lo)*(Li*Nd*Nk) + (li*Nd+nd)*Nk + nk
__global__ void k_conv(const float* __restrict__ kern,
                       int B, int Li, int Nd, int Lo, int Nk) {
    int total = B * Lo * Li * Nd * Nk;
    int i = blockIdx.x * blockDim.x + threadIdx.x;
    if (i >= total) return;
    int nk = i % Nk; int t = i / Nk;
    int nd = t % Nd; t /= Nd;
    int li = t % Li; t /= Li;
    int lo = t % Lo; int b = t / Lo;

    int di = (b * Li + li) * Nd + nd;
    float wd = g_SW[di], pdx = g_SPX[di], pdy = g_SPY[di];
    float d00 = g_SC00[di], d01 = g_SC01[di], d10 = g_SC10[di], d11 = g_SC11[di];

    const float* kp = kern + (((lo * Li + li) * Nk) + nk) * 7;
    float wk = kp[0], pkx = kp[1], pky = kp[2];
    float k00 = kp[3], k01 = kp[4], k10 = kp[5], k11 = kp[6];

    float s00 = d00 + k00, s01 = d01 + k01, s10 = d10 + k10, s11 = d11 + k11;
    float dd = d00 * d11 - d01 * d10;
    float dk = k00 * k11 - k01 * k10;
    float ds = s00 * s11 - s01 * s10;
    float ws = wd * wk * TWO_PI * sqrtf(dd * dk / fmaxf(ds, EPS));

    int o = (b * Lo + lo) * (Li * Nd * Nk) + (li * Nd + nd) * Nk + nk;
    g_W[o] = ws;
    g_PX[o] = pdx + pkx; g_PY[o] = pdy + pky;
    g_C00[o] = s00; g_C01[o] = s01; g_C10[o] = s10; g_C11[o] = s11;

    // folded inverse-covariance coefficients for eval:
    // exp(-0.5*md) = exp2(EA*dx^2 + EB*dx*dy + EC*dy^2)
    float inv = 1.0f / ds;
    g_EA[o] = NEG_HALF_LOG2E * s11 * inv;
    g_EB[o] = -NEG_HALF_LOG2E * (s01 + s10) * inv;
    g_EC[o] = NEG_HALF_LOG2E * s00 * inv;
}

// ---------------- eval_at_centers + relu scaling ----------------
// grid: (chunks, rows). block: 128 threads, one k per thread.
// shared: per-n {px,py,EA,EB} as float4 and {EC,w} as float2.
__global__ void k_eval(int N, int Lo, const float* __restrict__ bias) {
    extern __shared__ __align__(16) float sh[];
    float4* s4 = (float4*)sh;
    float2* s2 = (float2*)(sh + 4 * N);

    int row = blockIdx.y;
    int base = row * N;
    for (int n = threadIdx.x; n < N; n += blockDim.x) {
        int g = base + n;
        s4[n] = make_float4(g_PX[g], g_PY[g], g_EA[g], g_EB[g]);
        s2[n] = make_float2(g_EC[g], g_W[g]);
    }
    __syncthreads();

    int k = blockIdx.x * blockDim.x + threadIdx.x;
    if (k >= N) return;

    float kx = s4[k].x, ky = s4[k].y;
    float acc0 = 0.0f, acc1 = 0.0f;
    int n = 0;
    for (; n + 2 <= N; n += 2) {
        float4 q0 = s4[n];     float2 r0 = s2[n];
        float4 q1 = s4[n + 1]; float2 r1 = s2[n + 1];
        float dx0 = q0.x - kx, dy0 = q0.y - ky;
        float dx1 = q1.x - kx, dy1 = q1.y - ky;
        float u0 = fmaf(q0.z, dx0, q0.w * dy0);
        float u1 = fmaf(q1.z, dx1, q1.w * dy1);
        float md0 = fmaf(dx0, u0, (r0.x * dy0) * dy0);
        float md1 = fmaf(dx1, u1, (r1.x * dy1) * dy1);
        acc0 = fmaf(r0.y, fast_exp2(md0), acc0);
        acc1 = fmaf(r1.y, fast_exp2(md1), acc1);
    }
    if (n < N) {
        float4 q = s4[n]; float2 r = s2[n];
        float dx = q.x - kx, dy = q.y - ky;
        float u = fmaf(q.z, dx, q.w * dy);
        float md = fmaf(dx, u, (r.x * dy) * dy);
        acc0 = fmaf(r.y, fast_exp2(md), acc0);
    }

    float v = acc0 + acc1 + bias[row % Lo];
    float scale = fmaxf(v, 0.0f) / (fabsf(v) + EPS);
    g_W2[base + k] = s2[k].y * scale;
}

// ---------------- top-k select + gather + per-row integral sums ----------------
// one block (128 threads) per row. iterative argmax over |w2|.
__global__ void k_topk(int N, int nsel, int compute_sig) {
    int row = blockIdx.x;
    int tid = threadIdx.x;
    int base = row * N;

    __shared__ float sval[640];
    __shared__ float rmax[128];
    __shared__ int   ridx[128];
    __shared__ int   selidx[32];
    __shared__ float sI[32], sSig[32];

    for (int n = tid; n < N; n += 128) sval[n] = fabsf(g_W2[base + n]);
    __syncthreads();

    for (int t = 0; t < nsel; t++) {
        float m = -1.0f; int mi = N;
        for (int n = tid; n < N; n += 128) {
            float v = sval[n];
            if (v > m) { m = v; mi = n; }
        }
        rmax[tid] = m; ridx[tid] = mi;
        __syncthreads();
        for (int s = 64; s > 0; s >>= 1) {
            if (tid < s) {
                float vo = rmax[tid + s]; int io = ridx[tid + s];
                if (vo > rmax[tid] || (vo == rmax[tid] && io < ridx[tid])) {
                    rmax[tid] = vo; ridx[tid] = io;
                }
            }
            __syncthreads();
        }
        if (tid == 0) {
            selidx[t] = ridx[0];
            sval[ridx[0]] = -2.0f;
        }
        __syncthreads();
    }

    if (tid < nsel) {
        int src = base + selidx[tid];
        int dst = row * nsel + tid;
        float w = g_W2[src];
        float c00 = g_C00[src], c01 = g_C01[src], c10 = g_C10[src], c11 = g_C11[src];
        g_SW[dst] = w;
        g_SPX[dst] = g_PX[src]; g_SPY[dst] = g_PY[src];
        g_SC00[dst] = c00; g_SC01[dst] = c01; g_SC10[dst] = c10; g_SC11[dst] = c11;
        float I = w * TWO_PI * sqrtf(fmaxf(c00 * c11 - c01 * c10, EPS));
        sI[tid] = fabsf(I);
        sSig[tid] = I;
    }
    __syncthreads();
    if (tid == 0) {
        float tot = 0.0f, sig = 0.0f;
        for (int t = 0; t < nsel; t++) { tot += sI[t]; sig += sSig[t]; }
        g_TOT[row] = tot;
        if (compute_sig) g_SIG[row] = sig;
    }
}

// ---------------- batchnorm(per_gaussian=False): scale selected weights ----------------
// one block per li channel; scale = 1/(mean_b tot + eps)
__global__ void k_bnapply(int Li, int B, int nsel) {
    int li = blockIdx.x;
    int tid = threadIdx.x;
    __shared__ float ssc;
    if (tid == 0) {
        float t = 0.0f;
        for (int b = 0; b < B; b++) t += g_TOT[b * Li + li];
        ssc = 1.0f / (t / (float)B + EPS);
    }
    __syncthreads();
    float sc = ssc;
    int tot = B * nsel;
    for (int i = tid; i < tot; i += blockDim.x) {
        int b = i / nsel, n = i % nsel;
        g_SW[(b * Li + li) * nsel + n] *= sc;
    }
}

// ---------------- final: batchnorm + integrate + log_softmax ----------------
// rows = b*10+lo; one block, 320 threads.
__global__ void k_final(float* __restrict__ out) {
    int tid = threadIdx.x; // 0..319
    __shared__ float scl[10];
    __shared__ float logit[320];
    if (tid < 10) {
        float t = 0.0f;
        for (int b = 0; b < 32; b++) t += g_TOT[b * 10 + tid];
        scl[tid] = 1.0f / (t / 32.0f + EPS);
    }
    __syncthreads();
    logit[tid] = g_SIG[tid] * scl[tid % 10];
    __syncthreads();
    if (tid < 32) {
        int b = tid;
        float mx = -INFINITY;
        for (int l = 0; l < 10; l++) mx = fmaxf(mx, logit[b * 10 + l]);
        float se = 0.0f;
        for (int l = 0; l < 10; l++) se += expf(logit[b * 10 + l] - mx);
        float lse = mx + logf(se);
        for (int l = 0; l < 10; l++) out[b * 10 + l] = logit[b * 10 + l] - lse;
    }
}

extern "C" void kernel_launch(void* const* d_in, const int* in_sizes, int n_in,
                              void* d_out, int out_size) {
    const float* in_x = (const float*)d_in[0];
    const float* k1 = (const float*)d_in[1];
    const float* k2 = (const float*)d_in[2];
    const float* k3 = (const float*)d_in[3];
    const float* b1 = (const float*)d_in[4];
    const float* b2 = (const float*)d_in[5];
    const float* b3 = (const float*)d_in[6];
    float* out = (float*)d_out;

    // input batchnorm (per_gaussian=True): (32,1,64)
    k_bn_input<<<32, 64>>>(in_x);

    // ===== layer 1: B=32, Li=1, Nd=64, Lo=5, Nk=5 -> N=320, rows=160 =====
    {
        int B = 32, Li = 1, Nd = 64, Lo = 5, Nk = 5;
        int total = B * Lo * Li * Nd * Nk; // 51200
        int N = Li * Nd * Nk;              // 320
        int rows = B * Lo;                 // 160
        k_conv<<<(total + 255) / 256, 256>>>(k1, B, Li, Nd, Lo, Nk);
        dim3 eg((N + 127) / 128, rows);
        k_eval<<<eg, 128, N * 24>>>(N, Lo, b1);
        k_topk<<<rows, 128>>>(N, 25, 0);
        k_bnapply<<<Lo, 128>>>(Lo, B, 25);
    }

    // ===== layer 2: Li=5, Nd=25, Lo=6, Nk=5 -> N=625, rows=192 =====
    {
        int B = 32, Li = 5, Nd = 25, Lo = 6, Nk = 5;
        int total = B * Lo * Li * Nd * Nk; // 120000
        int N = Li * Nd * Nk;              // 625
        int rows = B * Lo;                 // 192
        k_conv<<<(total + 255) / 256, 256>>>(k2, B, Li, Nd, Lo, Nk);
        dim3 eg((N + 127) / 128, rows);
        k_eval<<<eg, 128, N * 24>>>(N, Lo, b2);
        k_topk<<<rows, 128>>>(N, 12, 0);
        k_bnapply<<<Lo, 128>>>(Lo, B, 12);
    }

    // ===== layer 3: Li=6, Nd=12, Lo=10, Nk=5 -> N=360, rows=320 =====
    {
        int B = 32, Li = 6, Nd = 12, Lo = 10, Nk = 5;
        int total = B * Lo * Li * Nd * Nk; // 115200
        int N = Li * Nd * Nk;              // 360
        int rows = B * Lo;                 // 320
        k_conv<<<(total + 255) / 256, 256>>>(k3, B, Li, Nd, Lo, Nk);
        dim3 eg((N + 127) / 128, rows);
        k_eval<<<eg, 128, N * 24>>>(N, Lo, b3);
        k_topk<<<rows, 128>>>(N, 5, 1);
    }

    // final batchnorm + integrate + log_softmax -> (32,10)
    k_final<<<1, 320>>>(out);
}

// round 3
// speedup vs baseline: 1.2889x; 1.2889x over previous
#include <cuda_runtime.h>
#include <math.h>

#define TWO_PI 6.283185307179586f
#define EPS 1e-6f
#define NEG_HALF_LOG2E (-0.7213475204444817f)

typedef unsigned long long u64;

// ---------------- device scratch ----------------
#define MAXM 120000
#define MAXS 4096
#define MAXROWS 320

__device__ float g_W[MAXM], g_PX[MAXM], g_PY[MAXM];
__device__ float g_C00[MAXM], g_C01[MAXM], g_C10[MAXM], g_C11[MAXM];
__device__ float g_EA[MAXM], g_EB[MAXM], g_EC[MAXM];
__device__ float g_W2[MAXM];

__device__ float g_SW[MAXS], g_SPX[MAXS], g_SPY[MAXS];
__device__ float g_SC00[MAXS], g_SC01[MAXS], g_SC10[MAXS], g_SC11[MAXS];

__device__ float g_TOT[MAXROWS], g_SIG[MAXROWS];

__device__ __forceinline__ float fast_exp2(float x) {
    float y;
    asm("ex2.approx.ftz.f32 %0, %1;" : "=f"(y) : "f"(x));
    return y;
}

// ---- packed f32x2 helpers (sm_103a FFMA2 path, PTX-only) ----
__device__ __forceinline__ u64 pk2(float lo, float hi) {
    u64 r; asm("mov.b64 %0, {%1, %2};" : "=l"(r) : "f"(lo), "f"(hi)); return r;
}
__device__ __forceinline__ void upk2(u64 v, float& lo, float& hi) {
    asm("mov.b64 {%0, %1}, %2;" : "=f"(lo), "=f"(hi) : "l"(v));
}
__device__ __forceinline__ u64 add2(u64 a, u64 b) {
    u64 r; asm("add.rn.f32x2 %0, %1, %2;" : "=l"(r) : "l"(a), "l"(b)); return r;
}
__device__ __forceinline__ u64 mul2(u64 a, u64 b) {
    u64 r; asm("mul.rn.f32x2 %0, %1, %2;" : "=l"(r) : "l"(a), "l"(b)); return r;
}
__device__ __forceinline__ u64 fma2(u64 a, u64 b, u64 c) {
    u64 r; asm("fma.rn.f32x2 %0, %1, %2, %3;" : "=l"(r) : "l"(a), "l"(b), "l"(c)); return r;
}

// ---------------- K1: batchnorm(per_gaussian=True) on input ----------------
__global__ void k_bn_input(const float* __restrict__ in_x) {
    int b = blockIdx.x;
    int n = threadIdx.x; // 0..63
    const float* m = in_x + (b * 64 + n) * 7;
    float w = m[0], px = m[1], py = m[2];
    float c00 = m[3], c01 = m[4], c10 = m[5], c11 = m[6];
    float det = c00 * c11 - c01 * c10;
    float I = w * TWO_PI * sqrtf(fmaxf(det, EPS));

    __shared__ float sh[64];
    sh[n] = fabsf(I);
    __syncthreads();
    for (int s = 32; s > 0; s >>= 1) {
        if (n < s) sh[n] += sh[n + s];
        __syncthreads();
    }
    float tot = sh[0];

    int idx = b * 64 + n;
    g_SW[idx]   = w / (tot + EPS);
    g_SPX[idx]  = px;  g_SPY[idx]  = py;
    g_SC00[idx] = c00; g_SC01[idx] = c01;
    g_SC10[idx] = c10; g_SC11[idx] = c11;
}

// ---------------- conv ----------------
__global__ void k_conv(const float* __restrict__ kern,
                       int B, int Li, int Nd, int Lo, int Nk) {
    int total = B * Lo * Li * Nd * Nk;
    int i = blockIdx.x * blockDim.x + threadIdx.x;
    if (i >= total) return;
    int nk = i % Nk; int t = i / Nk;
    int nd = t % Nd; t /= Nd;
    int li = t % Li; t /= Li;
    int lo = t % Lo; int b = t / Lo;

    int di = (b * Li + li) * Nd + nd;
    float wd = g_SW[di], pdx = g_SPX[di], pdy = g_SPY[di];
    float d00 = g_SC00[di], d01 = g_SC01[di], d10 = g_SC10[di], d11 = g_SC11[di];

    const float* kp = kern + (((lo * Li + li) * Nk) + nk) * 7;
    float wk = kp[0], pkx = kp[1], pky = kp[2];
    float k00 = kp[3], k01 = kp[4], k10 = kp[5], k11 = kp[6];

    float s00 = d00 + k00, s01 = d01 + k01, s10 = d10 + k10, s11 = d11 + k11;
    float dd = d00 * d11 - d01 * d10;
    float dk = k00 * k11 - k01 * k10;
    float ds = s00 * s11 - s01 * s10;
    float ws = wd * wk * TWO_PI * sqrtf(dd * dk / fmaxf(ds, EPS));

    int o = (b * Lo + lo) * (Li * Nd * Nk) + (li * Nd + nd) * Nk + nk;
    g_W[o] = ws;
    g_PX[o] = pdx + pkx; g_PY[o] = pdy + pky;
    g_C00[o] = s00; g_C01[o] = s01; g_C10[o] = s10; g_C11[o] = s11;

    float inv = 1.0f / ds;
    g_EA[o] = NEG_HALF_LOG2E * s11 * inv;
    g_EB[o] = -NEG_HALF_LOG2E * (s01 + s10) * inv;
    g_EC[o] = NEG_HALF_LOG2E * s00 * inv;
}

// ---------------- eval_at_centers + relu scaling (f32x2 packed) ----------------
// shared: 3 float4 arrays, pair-interleaved (6 floats per component = Np*24 bytes):
//   sA[j] = (px[2j], px[2j+1], py[2j], py[2j+1])
//   sB[j] = (ea[2j], ea[2j+1], eb[2j], eb[2j+1])
//   sC[j] = (ec[2j], ec[2j+1],  w[2j],  w[2j+1])
__global__ void k_eval(int N, int Lo, const float* __restrict__ bias) {
    extern __shared__ __align__(16) float sh[];
    int Np = (N + 1) & ~1;
    int half = Np >> 1;
    float* sAf = sh;
    float* sBf = sh + 2 * Np;
    float* sCf = sh + 4 * Np;

    int row = blockIdx.y;
    int base = row * N;
    for (int n = threadIdx.x; n < Np; n += blockDim.x) {
        int j4 = (n >> 1) * 4 + (n & 1);
        if (n < N) {
            int g = base + n;
            sAf[j4] = g_PX[g]; sAf[j4 + 2] = g_PY[g];
            sBf[j4] = g_EA[g]; sBf[j4 + 2] = g_EB[g];
            sCf[j4] = g_EC[g]; sCf[j4 + 2] = g_W[g];
        } else {
            sAf[j4] = 0.0f; sAf[j4 + 2] = 0.0f;
            sBf[j4] = 0.0f; sBf[j4 + 2] = 0.0f;
            sCf[j4] = 0.0f; sCf[j4 + 2] = 0.0f;
        }
    }
    __syncthreads();

    int k = blockIdx.x * blockDim.x + threadIdx.x;
    if (k >= N) return;

    int k4 = (k >> 1) * 4 + (k & 1);
    float kx = sAf[k4], ky = sAf[k4 + 2];
    float wk = sCf[k4 + 2];
    u64 nkx2 = pk2(-kx, -kx);
    u64 nky2 = pk2(-ky, -ky);
    u64 acc = 0ull; // (+0.0f, +0.0f)

    const float4* sA = (const float4*)sAf;
    const float4* sB = (const float4*)sBf;
    const float4* sC = (const float4*)sCf;

    #pragma unroll 4
    for (int j = 0; j < half; j++) {
        float4 a = sA[j];
        float4 bq = sB[j];
        float4 c = sC[j];
        u64 px2 = *(const u64*)&a.x;  u64 py2 = *(const u64*)&a.z;
        u64 ea2 = *(const u64*)&bq.x; u64 eb2 = *(const u64*)&bq.z;
        u64 ec2 = *(const u64*)&c.x;  u64 w2p = *(const u64*)&c.z;

        u64 dx = add2(px2, nkx2);
        u64 dy = add2(py2, nky2);
        u64 u  = fma2(ea2, dx, mul2(eb2, dy));
        u64 md = fma2(dx, u, mul2(mul2(ec2, dy), dy));
        float m0, m1; upk2(md, m0, m1);
        u64 e = pk2(fast_exp2(m0), fast_exp2(m1));
        acc = fma2(w2p, e, acc);
    }

    float a0, a1; upk2(acc, a0, a1);
    float v = a0 + a1 + bias[row % Lo];
    float scale = fmaxf(v, 0.0f) / (fabsf(v) + EPS);
    g_W2[base + k] = wk * scale;
}

// ---------------- top-k: one warp per row, shuffle-only ----------------
// block = 128 threads = 4 warps = 4 rows. Values register-resident.
__global__ void k_topk(int N, int nsel, int compute_sig, int rows) {
    int warp = threadIdx.x >> 5;
    int lane = threadIdx.x & 31;
    int row = blockIdx.x * 4 + warp;
    if (row >= rows) return;
    int base = row * N;

    // K = ceil(N/32) <= 20 ; n = lane + j*32
    float v[20];
    int K = (N + 31) >> 5;
    for (int j = 0; j < K; j++) {
        int n = lane + (j << 5);
        v[j] = (n < N) ? fabsf(g_W2[base + n]) : -1.0f;
    }

    int selN = -1;
    for (int t = 0; t < nsel; t++) {
        // local argmax (lowest j on tie -> lowest n within lane)
        float m = -1.0f; int bi = 0x7fffffff;
        for (int j = 0; j < K; j++) {
            if (v[j] > m) { m = v[j]; bi = lane + (j << 5); }
        }
        // warp argmax with lowest-index tiebreak
        for (int off = 16; off > 0; off >>= 1) {
            float mo = __shfl_xor_sync(0xffffffffu, m, off);
            int io = __shfl_xor_sync(0xffffffffu, bi, off);
            if (mo > m || (mo == m && io < bi)) { m = mo; bi = io; }
        }
        // owner invalidates
        if (lane == (bi & 31)) v[bi >> 5] = -2.0f;
        // lane t records this selection
        if (lane == t) selN = bi;
    }

    // parallel gather + per-row sums
    float aI = 0.0f, sI = 0.0f;
    if (lane < nsel) {
        int src = base + selN;
        int dst = row * nsel + lane;
        float w = g_W2[src];
        float c00 = g_C00[src], c01 = g_C01[src], c10 = g_C10[src], c11 = g_C11[src];
        g_SW[dst] = w;
        g_SPX[dst] = g_PX[src]; g_SPY[dst] = g_PY[src];
        g_SC00[dst] = c00; g_SC01[dst] = c01; g_SC10[dst] = c10; g_SC11[dst] = c11;
        float I = w * TWO_PI * sqrtf(fmaxf(c00 * c11 - c01 * c10, EPS));
        aI = fabsf(I); sI = I;
    }
    for (int off = 16; off > 0; off >>= 1) {
        aI += __shfl_xor_sync(0xffffffffu, aI, off);
        sI += __shfl_xor_sync(0xffffffffu, sI, off);
    }
    if (lane == 0) {
        g_TOT[row] = aI;
        if (compute_sig) g_SIG[row] = sI;
    }
}

// ---------------- batchnorm(per_gaussian=False) apply ----------------
__global__ void k_bnapply(int Li, int B, int nsel) {
    int li = blockIdx.x;
    int tid = threadIdx.x;
    __shared__ float ssc;
    if (tid == 0) {
        float t = 0.0f;
        for (int b = 0; b < B; b++) t += g_TOT[b * Li + li];
        ssc = 1.0f / (t / (float)B + EPS);
    }
    __syncthreads();
    float sc = ssc;
    int tot = B * nsel;
    for (int i = tid; i < tot; i += blockDim.x) {
        int b = i / nsel, n = i % nsel;
        g_SW[(b * Li + li) * nsel + n] *= sc;
    }
}

// ---------------- final: batchnorm + integrate + log_softmax ----------------
__global__ void k_final(float* __restrict__ out) {
    int tid = threadIdx.x; // 0..319
    __shared__ float scl[10];
    __shared__ float logit[320];
    if (tid < 10) {
        float t = 0.0f;
        for (int b = 0; b < 32; b++) t += g_TOT[b * 10 + tid];
        scl[tid] = 1.0f / (t / 32.0f + EPS);
    }
    __syncthreads();
    logit[tid] = g_SIG[tid] * scl[tid % 10];
    __syncthreads();
    if (tid < 32) {
        int b = tid;
        float mx = -INFINITY;
        for (int l = 0; l < 10; l++) mx = fmaxf(mx, logit[b * 10 + l]);
        float se = 0.0f;
        for (int l = 0; l < 10; l++) se += expf(logit[b * 10 + l] - mx);
        float lse = mx + logf(se);
        for (int l = 0; l < 10; l++) out[b * 10 + l] = logit[b * 10 + l] - lse;
    }
}

extern "C" void kernel_launch(void* const* d_in, const int* in_sizes, int n_in,
                              void* d_out, int out_size) {
    const float* in_x = (const float*)d_in[0];
    const float* k1 = (const float*)d_in[1];
    const float* k2 = (const float*)d_in[2];
    const float* k3 = (const float*)d_in[3];
    const float* b1 = (const float*)d_in[4];
    const float* b2 = (const float*)d_in[5];
    const float* b3 = (const float*)d_in[6];
    float* out = (float*)d_out;

    k_bn_input<<<32, 64>>>(in_x);

    // ===== layer 1: B=32, Li=1, Nd=64, Lo=5, Nk=5 -> N=320, rows=160 =====
    {
        int B = 32, Li = 1, Nd = 64, Lo = 5, Nk = 5;
        int total = B * Lo * Li * Nd * Nk;
        int N = Li * Nd * Nk;
        int rows = B * Lo;
        int Np = (N + 1) & ~1;
        k_conv<<<(total + 255) / 256, 256>>>(k1, B, Li, Nd, Lo, Nk);
        dim3 eg((N + 127) / 128, rows);
        k_eval<<<eg, 128, Np * 24>>>(N, Lo, b1);
        k_topk<<<(rows + 3) / 4, 128>>>(N, 25, 0, rows);
        k_bnapply<<<Lo, 128>>>(Lo, B, 25);
    }

    // ===== layer 2: Li=5, Nd=25, Lo=6, Nk=5 -> N=625, rows=192 =====
    {
        int B = 32, Li = 5, Nd = 25, Lo = 6, Nk = 5;
        int total = B * Lo * Li * Nd * Nk;
        int N = Li * Nd * Nk;
        int rows = B * Lo;
        int Np = (N + 1) & ~1;
        k_conv<<<(total + 255) / 256, 256>>>(k2, B, Li, Nd, Lo, Nk);
        dim3 eg((N + 127) / 128, rows);
        k_eval<<<eg, 128, Np * 24>>>(N, Lo, b2);
        k_topk<<<(rows + 3) / 4, 128>>>(N, 12, 0, rows);
        k_bnapply<<<Lo, 128>>>(Lo, B, 12);
    }

    // ===== layer 3: Li=6, Nd=12, Lo=10, Nk=5 -> N=360, rows=320 =====
    {
        int B = 32, Li = 6, Nd = 12, Lo = 10, Nk = 5;
        int total = B * Lo * Li * Nd * Nk;
        int N = Li * Nd * Nk;
        int rows = B * Lo;
        int Np = (N + 1) & ~1;
        k_conv<<<(total + 255) / 256, 256>>>(k3, B, Li, Nd, Lo, Nk);
        dim3 eg((N + 127) / 128, rows);
        k_eval<<<eg, 128, Np * 24>>>(N, Lo, b3);
        k_topk<<<(rows + 3) / 4, 128>>>(N, 5, 1, rows);
    }

    k_final<<<1, 320>>>(out);
}